// round 5
// baseline (speedup 1.0000x reference)
#include <cuda_runtime.h>
#include <cstdint>
#include <cstddef>

#define B_ 256
#define S_ 512
#define T_ 128

typedef unsigned long long ull;

__device__ float g_acc;
__device__ int g_tag64;        // 1 if tags buffer is int64, 0 if int32
__device__ int g_mask_stride;  // 1 if mask is bool/uint8, 4 if int32

// Packed fp32x2 ops (sm_103a): ptxas won't auto-fuse these from C++.
#define FMA2(d, a, b, c) asm("fma.rn.f32x2 %0, %1, %2, %3;" : "=l"(d) : "l"(a), "l"(b), "l"(c))
#define ADD2(d, a, b)    asm("add.rn.f32x2 %0, %1, %2;"     : "=l"(d) : "l"(a), "l"(b))
#define PACK2(d, lo, hi) asm("mov.b64 %0, {%1, %2};"        : "=l"(d) : "f"(lo), "f"(hi))
#define UNPK2(lo, hi, s) asm("mov.b64 {%0, %1}, %2;"        : "=f"(lo), "=f"(hi) : "l"(s))

// ---------------------------------------------------------------------------
// Runtime dtype probe. JAX with x64 disabled silently downcasts the reference's
// jnp.int64 tags to int32; the bool mask may be 1 byte or (defensively) int32.
// Tags values are in [0,128), so if the buffer is int64 every odd int32 word is
// zero; for genuine int32 data P(first 64 odd words all zero) = 128^-64 ~ 0.
// Probe touches only the first 256 bytes -> safe under either layout.
// ---------------------------------------------------------------------------
__global__ void detect_kernel(const int* __restrict__ tags32,
                              const unsigned char* __restrict__ mk) {
    int all0 = 1;
    #pragma unroll
    for (int i = 0; i < 64; ++i)
        if (tags32[2 * i + 1] != 0) all0 = 0;
    g_tag64 = all0;
    // all-true bool mask: bytes 01 01 01 01...; int32 mask: 01 00 00 00...
    g_mask_stride = (mk[0] != 0 && mk[1] == 0 && mk[2] == 0 && mk[3] == 0) ? 4 : 1;
    g_acc = 0.0f;
}

// ---------------------------------------------------------------------------
// Gold score: sum(emissions[b,t,tag] * m) + sum(T[tag_t, tag_{t+1}] * m[t+1])
// Accumulated NEGATIVE into g_acc.
// ---------------------------------------------------------------------------
__global__ void gold_kernel(const float* __restrict__ em,
                            const void* __restrict__ tags,
                            const unsigned char* __restrict__ mask,
                            const float* __restrict__ tr) {
    const int b = blockIdx.x;
    const int tid = threadIdx.x;
    const int t64 = g_tag64;
    const int mst = g_mask_stride;
    const long long* tg64 = (const long long*)tags + (size_t)b * S_;
    const int*       tg32 = (const int*)tags + (size_t)b * S_;
    const unsigned char* mk = mask + (size_t)b * S_ * mst;

    float sum = 0.0f;
    for (int t = tid; t < S_; t += blockDim.x) {
        int tag  = t64 ? (int)tg64[t] : tg32[t];
        float m  = mk[(size_t)t * mst] ? 1.0f : 0.0f;
        sum += em[((size_t)b * S_ + t) * T_ + tag] * m;
        if (t + 1 < S_) {
            int tag2 = t64 ? (int)tg64[t + 1] : tg32[t + 1];
            float m2 = mk[(size_t)(t + 1) * mst] ? 1.0f : 0.0f;
            sum += tr[tag * T_ + tag2] * m2;
        }
    }
    for (int off = 16; off; off >>= 1)
        sum += __shfl_xor_sync(0xffffffffu, sum, off);
    __shared__ float ws[8];
    if ((tid & 31) == 0) ws[tid >> 5] = sum;
    __syncthreads();
    if (tid == 0) {
        float s = 0.0f;
        #pragma unroll
        for (int w = 0; w < 8; ++w) s += ws[w];
        atomicAdd(&g_acc, -s);
    }
}

// ---------------------------------------------------------------------------
// Forward partition in rescaled linear space.
// One CTA handles 2 batch rows. 256 threads:
//   compute role: jp = tid & 63 (j-pair 2jp,2jp+1), q = tid >> 6 (i-quarter)
//   stage2 role (tid < 128): b2 = tid >> 6, same jp
// M = exp(T) lives in registers (32 f32x2 per thread, shared by both batches).
// alpha stored DUPLICATED in smem: (a_i, a_i) so the packed FMA operand is a
// single broadcast LDS.64. Rescaling is self-consistent (inv and logacc use the
// same m), so it contributes zero bias by construction.
// ---------------------------------------------------------------------------
__global__ void __launch_bounds__(256, 1) crf_forward(
    const float* __restrict__ em, const float* __restrict__ tr) {

    __shared__ __align__(16) float2 s_alpha[2][T_];  // duplicated alpha per batch
    __shared__ __align__(16) ull    s_part[4][2][64];
    __shared__ __align__(16) float  s_emb[2][2][T_]; // double-buffered emissions
    __shared__ float s_wmax[2][2];
    __shared__ float s_fsum[4];

    const int tid = threadIdx.x;
    const int jp  = tid & 63;
    const int q   = tid >> 6;
    const int col = tid & 127;
    const int bb  = tid >> 7;              // local batch for prefetch role
    const int gb0 = blockIdx.x * 2;
    const size_t gbp = (size_t)(gb0 + bb); // prefetch batch row
    const int b2  = tid >> 6;              // stage2 batch (valid tid<128)

    // --- load exp(T) column-pair chunk into registers -----------------------
    ull Mreg[32];
    {
        const int j0 = 2 * jp;
        #pragma unroll
        for (int k = 0; k < 32; ++k) {
            int i = 32 * q + k;
            float m0 = expf(tr[i * T_ + j0]);
            float m1 = expf(tr[i * T_ + j0 + 1]);
            PACK2(Mreg[k], m0, m1);
        }
    }

    // --- prefetch emissions t=0,1 into smem, t=2 into register -------------
    s_emb[0][bb][col] = em[(gbp * S_ + 0) * T_ + col];
    s_emb[1][bb][col] = em[(gbp * S_ + 1) * T_ + col];
    float r_e = em[(gbp * S_ + 2) * T_ + col];
    __syncthreads();

    // --- init: alpha_hat_0 = exp(e0 - max(e0)), logacc = max(e0) -----------
    float logacc = 0.0f, v0 = 0.0f, v1 = 0.0f;
    if (tid < 128) {
        float2 e2 = *(const float2*)&s_emb[0][b2][2 * jp];
        float pm = fmaxf(e2.x, e2.y);
        for (int off = 16; off; off >>= 1)
            pm = fmaxf(pm, __shfl_xor_sync(0xffffffffu, pm, off));
        if ((tid & 31) == 0) s_wmax[b2][(tid >> 5) & 1] = pm;
    }
    __syncthreads();
    if (tid < 128) {
        float m0 = fmaxf(s_wmax[b2][0], s_wmax[b2][1]);
        float2 e2 = *(const float2*)&s_emb[0][b2][2 * jp];
        float a0 = __expf(e2.x - m0);
        float a1 = __expf(e2.y - m0);
        float4 w4 = make_float4(a0, a0, a1, a1);
        *(float4*)&s_alpha[b2][2 * jp] = w4;
        if (jp == 0) logacc = m0;
    }
    __syncthreads();
    if (tid < 4) s_wmax[tid >> 1][tid & 1] = 1.0f;  // m_0 := 1 (alpha max = 1)
    __syncthreads();

    const ull* A0 = (const ull*)&s_alpha[0][32 * q];
    const ull* A1 = (const ull*)&s_alpha[1][32 * q];

    // --- main recursion -----------------------------------------------------
    for (int t = 1; t < S_; ++t) {
        const int buf = t & 1;

        // stage-0: scale factor + emission exps (independent of this step's matvec)
        float inv = 0.0f, ex0 = 0.0f, ex1 = 0.0f;
        if (tid < 128) {
            float m = fmaxf(s_wmax[b2][0], s_wmax[b2][1]);
            inv = __fdividef(1.0f, m);
            if (jp == 0) logacc += __logf(m);
            float2 e2 = *(const float2*)&s_emb[buf][b2][2 * jp];
            ex0 = __expf(e2.x);
            ex1 = __expf(e2.y);
        }

        // rotate emission prefetch ring (e[t+1] -> smem, fetch e[t+2])
        s_emb[buf ^ 1][bb][col] = r_e;
        {
            int t2 = t + 2; if (t2 > S_ - 1) t2 = S_ - 1;
            r_e = em[(gbp * S_ + t2) * T_ + col];
        }

        // inner matvec: both batches, packed j-pairs
        ull acc00 = 0ull, acc01 = 0ull, acc10 = 0ull, acc11 = 0ull;
        #pragma unroll
        for (int k = 0; k < 32; k += 2) {
            FMA2(acc00, A0[k],     Mreg[k],     acc00);
            FMA2(acc10, A1[k],     Mreg[k],     acc10);
            FMA2(acc01, A0[k + 1], Mreg[k + 1], acc01);
            FMA2(acc11, A1[k + 1], Mreg[k + 1], acc11);
        }
        ull acc0, acc1;
        ADD2(acc0, acc00, acc01);
        ADD2(acc1, acc10, acc11);
        s_part[q][0][jp] = acc0;
        s_part[q][1][jp] = acc1;
        __syncthreads();

        // stage-2: reduce quarters, scale, emit, track max, write dup alpha
        if (tid < 128) {
            ull p0 = s_part[0][b2][jp], p1 = s_part[1][b2][jp];
            ull p2 = s_part[2][b2][jp], p3 = s_part[3][b2][jp];
            ull s01, s23, st;
            ADD2(s01, p0, p1);
            ADD2(s23, p2, p3);
            ADD2(st, s01, s23);
            float lo, hi;
            UNPK2(lo, hi, st);
            v0 = lo * inv * ex0;
            v1 = hi * inv * ex1;
            float pm = fmaxf(v0, v1);   // > 0, so uint compare == float compare
            unsigned wm = __reduce_max_sync(0xffffffffu, __float_as_uint(pm));
            if ((tid & 31) == 0) s_wmax[b2][(tid >> 5) & 1] = __uint_as_float(wm);
            float4 w4 = make_float4(v0, v0, v1, v1);
            *(float4*)&s_alpha[b2][2 * jp] = w4;
        }
        __syncthreads();
    }

    // --- finish: partition_b = log(sum_j raw_511) + logacc ------------------
    if (tid < 128) {
        float s = v0 + v1;
        for (int off = 16; off; off >>= 1)
            s += __shfl_xor_sync(0xffffffffu, s, off);
        if ((tid & 31) == 0) s_fsum[tid >> 5] = s;
    }
    __syncthreads();
    if (tid == 0) {
        float tot = s_fsum[0] + s_fsum[1];
        atomicAdd(&g_acc, logf(tot) + logacc);
    }
    if (tid == 64) {
        float tot = s_fsum[2] + s_fsum[3];
        atomicAdd(&g_acc, logf(tot) + logacc);
    }
}

__global__ void finish_kernel(float* out) { out[0] = g_acc; }

extern "C" void kernel_launch(void* const* d_in, const int* in_sizes, int n_in,
                              void* d_out, int out_size) {
    const float* em         = (const float*)d_in[0];
    const void* tags        = d_in[1];
    const unsigned char* mk = (const unsigned char*)d_in[2];
    const float* tr         = (const float*)d_in[3];

    detect_kernel<<<1, 1>>>((const int*)tags, mk);
    gold_kernel<<<B_, 256>>>(em, tags, mk, tr);
    crf_forward<<<B_ / 2, 256>>>(em, tr);
    finish_kernel<<<1, 1>>>((float*)d_out);
}

// round 8
// speedup vs baseline: 1.3042x; 1.3042x over previous
#include <cuda_runtime.h>
#include <cstdint>
#include <cstddef>

#define B_ 256
#define S_ 512
#define T_ 128

typedef unsigned long long ull;

__device__ float g_acc;
__device__ int g_tag64;        // 1 if tags buffer is int64, 0 if int32
__device__ int g_mask_stride;  // 1 if mask is bool/uint8, 4 if int32

// Packed fp32x2 ops (sm_103a): ptxas won't auto-fuse these from C++.
#define FMA2(d, a, b, c) asm("fma.rn.f32x2 %0, %1, %2, %3;" : "=l"(d) : "l"(a), "l"(b), "l"(c))
#define ADD2(d, a, b)    asm("add.rn.f32x2 %0, %1, %2;"     : "=l"(d) : "l"(a), "l"(b))
#define PACK2(d, lo, hi) asm("mov.b64 %0, {%1, %2};"        : "=l"(d) : "f"(lo), "f"(hi))
#define UNPK2(lo, hi, s) asm("mov.b64 {%0, %1}, %2;"        : "=f"(lo), "=f"(hi) : "l"(s))

// ---------------------------------------------------------------------------
// Runtime dtype probe (JAX x64-off silently downcasts int64 tags to int32).
// Touches only the first 256 bytes -> safe under either layout.
// ---------------------------------------------------------------------------
__global__ void detect_kernel(const int* __restrict__ tags32,
                              const unsigned char* __restrict__ mk) {
    int all0 = 1;
    #pragma unroll
    for (int i = 0; i < 64; ++i)
        if (tags32[2 * i + 1] != 0) all0 = 0;
    g_tag64 = all0;
    g_mask_stride = (mk[0] != 0 && mk[1] == 0 && mk[2] == 0 && mk[3] == 0) ? 4 : 1;
    g_acc = 0.0f;
}

// ---------------------------------------------------------------------------
// Forward partition + gold, one batch per CTA, 128 threads (thread = column j),
// 2 CTAs/SM for cross-CTA latency hiding. M column in 64 packed f32x2 regs.
// One __syncthreads per recursion step; alpha and wmax double-buffered.
// ---------------------------------------------------------------------------
__global__ void __launch_bounds__(128, 2) crf_forward(
    const float* __restrict__ em, const float* __restrict__ tr,
    const void* __restrict__ tags, const unsigned char* __restrict__ mask) {

    __shared__ __align__(16) float s_alpha[2][T_];
    __shared__ __align__(16) float s_wmax[2][4];
    __shared__ float s_red[4];

    const int j = threadIdx.x;       // 0..127 : output column
    const int w = j >> 5;            // warp id
    const size_t b = blockIdx.x;     // batch

    // ---- gold score for this batch (negated into g_acc) -------------------
    {
        const int t64 = g_tag64, mst = g_mask_stride;
        const long long* tg64 = (const long long*)tags + b * S_;
        const int*       tg32 = (const int*)tags + b * S_;
        const unsigned char* mk = mask + b * S_ * mst;
        float sum = 0.0f;
        for (int t = j; t < S_; t += 128) {
            int tag = t64 ? (int)tg64[t] : tg32[t];
            float m = mk[(size_t)t * mst] ? 1.0f : 0.0f;
            sum += em[(b * S_ + t) * T_ + tag] * m;
            if (t + 1 < S_) {
                int tag2 = t64 ? (int)tg64[t + 1] : tg32[t + 1];
                float m2 = mk[(size_t)(t + 1) * mst] ? 1.0f : 0.0f;
                sum += tr[tag * T_ + tag2] * m2;
            }
        }
        for (int off = 16; off; off >>= 1)
            sum += __shfl_xor_sync(0xffffffffu, sum, off);
        if ((j & 31) == 0) s_red[w] = sum;
        __syncthreads();
        if (j == 0)
            atomicAdd(&g_acc, -(s_red[0] + s_red[1] + s_red[2] + s_red[3]));
        __syncthreads();   // s_red reused below
    }

    // ---- M column j: Mc[k] = (exp(T[2k][j]), exp(T[2k+1][j])) --------------
    ull Mc[64];
    #pragma unroll
    for (int k = 0; k < 64; ++k) {
        float m0 = expf(tr[(2 * k) * T_ + j]);
        float m1 = expf(tr[(2 * k + 1) * T_ + j]);
        PACK2(Mc[k], m0, m1);
    }

    // ---- init: alpha_hat_0 = exp(e0 - max(e0)), logacc = max(e0) -----------
    float e0 = em[(b * S_ + 0) * T_ + j];
    float pm = e0;
    for (int off = 16; off; off >>= 1)
        pm = fmaxf(pm, __shfl_xor_sync(0xffffffffu, pm, off));
    if ((j & 31) == 0) s_red[w] = pm;
    __syncthreads();
    float m0v = fmaxf(fmaxf(s_red[0], s_red[1]), fmaxf(s_red[2], s_red[3]));
    float logacc = m0v;                    // all threads track; j==0's is used
    s_alpha[0][j] = __expf(e0 - m0v);
    if (j < 4) s_wmax[0][j] = 1.0f;        // max(alpha_hat_0) = 1

    // emission prefetch ring (3 deep)
    float e_cur = em[(b * S_ + 1) * T_ + j];
    float e_nx  = em[(b * S_ + 2) * T_ + j];
    float e_nx2 = em[(b * S_ + 3) * T_ + j];
    __syncthreads();

    // ---- main recursion: one barrier per step ------------------------------
    float v = 0.0f;
    #pragma unroll 1
    for (int t = 1; t < S_; ++t) {
        const int rb = (t - 1) & 1, wb = t & 1;

        float4 wm4 = *(const float4*)s_wmax[rb];
        float m   = fmaxf(fmaxf(wm4.x, wm4.y), fmaxf(wm4.z, wm4.w));
        float inv = __fdividef(1.0f, m);
        logacc += __logf(m);               // uniform across CTA, no divergence
        float ex = __expf(e_cur);

        // 128-long dot product: 32 broadcast LDS.128 + 64 FMA2, 4 acc chains
        const ulonglong2* A = (const ulonglong2*)s_alpha[rb];
        ull a0 = 0ull, a1 = 0ull, a2 = 0ull, a3 = 0ull;
        #pragma unroll
        for (int k = 0; k < 32; k += 2) {
            ulonglong2 p  = A[k];
            ulonglong2 q2 = A[k + 1];
            FMA2(a0, p.x,  Mc[2 * k],     a0);
            FMA2(a1, p.y,  Mc[2 * k + 1], a1);
            FMA2(a2, q2.x, Mc[2 * k + 2], a2);
            FMA2(a3, q2.y, Mc[2 * k + 3], a3);
        }
        ADD2(a0, a0, a1);
        ADD2(a2, a2, a3);
        ADD2(a0, a0, a2);
        float lo, hi;
        UNPK2(lo, hi, a0);
        v = (lo + hi) * inv * ex;

        // rotate prefetch ring
        e_cur = e_nx; e_nx = e_nx2;
        int t3 = (t + 3 < S_) ? t + 3 : S_ - 1;
        e_nx2 = em[(b * S_ + t3) * T_ + j];

        // publish alpha + warp max (v >= 0 so uint compare == float compare)
        s_alpha[wb][j] = v;
        unsigned wmx = __reduce_max_sync(0xffffffffu, __float_as_uint(v));
        if ((j & 31) == 0) s_wmax[wb][w] = __uint_as_float(wmx);
        __syncthreads();
    }

    // ---- finish: partition_b = log(sum_j v) + logacc -----------------------
    float s = v;
    for (int off = 16; off; off >>= 1)
        s += __shfl_xor_sync(0xffffffffu, s, off);
    if ((j & 31) == 0) s_red[w] = s;
    __syncthreads();
    if (j == 0) {
        float tot = s_red[0] + s_red[1] + s_red[2] + s_red[3];
        atomicAdd(&g_acc, logf(tot) + logacc);
    }
}

__global__ void finish_kernel(float* out) { out[0] = g_acc; }

extern "C" void kernel_launch(void* const* d_in, const int* in_sizes, int n_in,
                              void* d_out, int out_size) {
    const float* em         = (const float*)d_in[0];
    const void* tags        = d_in[1];
    const unsigned char* mk = (const unsigned char*)d_in[2];
    const float* tr         = (const float*)d_in[3];

    detect_kernel<<<1, 1>>>((const int*)tags, mk);
    crf_forward<<<B_, 128>>>(em, tr, tags, mk);
    finish_kernel<<<1, 1>>>((float*)d_out);
}